// round 15
// baseline (speedup 1.0000x reference)
#include <cuda_runtime.h>
#include <cuda_fp16.h>
#include <cstdint>

// ============================================================
// TorchRandomProject: out[4096,4096] = x[4096,2048] @ matrix[0][4096,2048]^T
// fp16 HMMA (same 10-bit mantissa as tf32 => same rel_err), fp32 accum.
// R15: R14 mbarrier pipeline + producer block (empty-wait + cp.asyncs +
// .noinc arrive) hoisted into the kk-loop midpoint (after kk2==1), so the
// ~140-cyc produce segment overlaps tensor work instead of serializing
// after compute. Safe: empty(stage i+2) depends on releases of chunk i-1,
// not this iteration's own release.
// ============================================================

#define B_DIM   4096
#define K_DIM   2048
#define O_DIM   4096

// 32MB device scratch for fp16 operands
__device__ __half g_xh[(size_t)B_DIM * K_DIM];
__device__ __half g_wh[(size_t)O_DIM * K_DIM];

// ---------------- tile config ----------------
#define BM 128
#define BN 128
#define BK 64                       // K halfs per chunk (128B row)
#define NSTAGE 3
#define NCHUNK (K_DIM / BK)         // 32
#define A_BYTES (BM * BK * 2)       // 16384
#define B_BYTES (BN * BK * 2)       // 16384
#define STAGE_BYTES (A_BYTES + B_BYTES)      // 32768 (= 1<<15)
#define SM_DATA0 1024               // stages start here (mbarriers below)
#define SMEM_TOTAL (SM_DATA0 + NSTAGE * STAGE_BYTES)  // 99328 (x2 CTA ok)

// ---------------- PTX helpers ----------------
__device__ __forceinline__ uint32_t smem_u32(const void* p) {
    uint32_t a;
    asm("{ .reg .u64 t; cvta.to.shared.u64 t, %1; cvt.u32.u64 %0, t; }" : "=r"(a) : "l"(p));
    return a;
}

__device__ __forceinline__ void cp_async16(uint32_t dst, const void* src) {
    asm volatile("cp.async.cg.shared.global [%0], [%1], 16;" :: "r"(dst), "l"(src) : "memory");
}

#define MBARRIER_INIT(addr, count) \
    asm volatile("mbarrier.init.shared.b64 [%0], %1;" :: "r"((uint32_t)(addr)), "r"((uint32_t)(count)) : "memory")

// .noinc: the deferred arrive (fires when this thread's prior cp.asyncs
// complete) counts toward the expected arrivals.
#define CP_ASYNC_MBAR_ARRIVE_NOINC(addr) \
    asm volatile("cp.async.mbarrier.arrive.noinc.shared.b64 [%0];" :: "r"((uint32_t)(addr)) : "memory")

#define MBARRIER_ARRIVE(addr) \
    asm volatile("mbarrier.arrive.shared.b64 _, [%0];" :: "r"((uint32_t)(addr)) : "memory")

#define MBARRIER_WAIT_PARITY(addr, parity) do { \
    uint32_t _mbar = (uint32_t)(addr); \
    uint32_t _par = (uint32_t)(parity); \
    uint32_t _done; \
    asm volatile("{\n\t.reg .pred p;\n\t" \
        "mbarrier.try_wait.parity.acquire.cta.shared::cta.b64 p, [%1], %2;\n\t" \
        "selp.b32 %0, 1, 0, p;\n\t}" : "=r"(_done) : "r"(_mbar), "r"(_par) : "memory"); \
    if (!_done) { \
        asm volatile("{\n\t.reg .pred P1;\n\t" \
            "WL_%=:\n\t" \
            "mbarrier.try_wait.parity.acquire.cta.shared::cta.b64 P1, [%0], %1, 0x989680;\n\t" \
            "@P1 bra.uni WD_%=;\n\t" \
            "bra.uni WL_%=;\n\t" \
            "WD_%=:\n\t}" :: "r"(_mbar), "r"(_par) : "memory"); \
    } \
} while (0)

__device__ __forceinline__ void ldsm4(uint32_t r[4], uint32_t addr) {
    asm volatile("ldmatrix.sync.aligned.m8n8.x4.shared.b16 {%0,%1,%2,%3}, [%4];"
                 : "=r"(r[0]), "=r"(r[1]), "=r"(r[2]), "=r"(r[3]) : "r"(addr));
}

__device__ __forceinline__ void mma_f16(float c[4], const uint32_t a[4],
                                        uint32_t b0, uint32_t b1) {
    asm volatile(
        "mma.sync.aligned.m16n8k16.row.col.f32.f16.f16.f32 "
        "{%0,%1,%2,%3}, {%4,%5,%6,%7}, {%8,%9}, {%0,%1,%2,%3};"
        : "+f"(c[0]), "+f"(c[1]), "+f"(c[2]), "+f"(c[3])
        : "r"(a[0]), "r"(a[1]), "r"(a[2]), "r"(a[3]), "r"(b0), "r"(b1));
}

// ---------------- prep: fp32 -> fp16 (rne) ----------------
__global__ void cvt_f16_kernel(const float* __restrict__ x, const float* __restrict__ w) {
    size_t i = (size_t)blockIdx.x * blockDim.x + threadIdx.x;  // over 2M float4
    float4 a = reinterpret_cast<const float4*>(x)[i];
    reinterpret_cast<__half2*>(g_xh)[2 * i + 0] = __floats2half2_rn(a.x, a.y);
    reinterpret_cast<__half2*>(g_xh)[2 * i + 1] = __floats2half2_rn(a.z, a.w);
    float4 b = reinterpret_cast<const float4*>(w)[i];
    reinterpret_cast<__half2*>(g_wh)[2 * i + 0] = __floats2half2_rn(b.x, b.y);
    reinterpret_cast<__half2*>(g_wh)[2 * i + 1] = __floats2half2_rn(b.z, b.w);
}

// ---------------- GEMM ----------------
// mbarriers: full[s] = sbase + s*16 (count 256, .noinc arrive-on per thread),
// empty[s] = +8 (count 8, lane-0 arrive per warp).
// stage data at sbase + SM_DATA0; A then B, 128B rows, XOR-16B swizzle.

__device__ __forceinline__ void load_half(int tid, uint32_t sdst,
                                          const __half* __restrict__ G,
                                          size_t koff) {
#pragma unroll
    for (int q = 0; q < 4; q++) {            // 128 rows x 8 x 16B
        int idx = tid + q * 256;
        int row = idx >> 3, ch = idx & 7;
        uint32_t dst = sdst + (uint32_t)row * 128u + (uint32_t)((ch ^ (row & 7)) << 4);
        cp_async16(dst, G + (size_t)row * K_DIM + koff + ch * 8);
    }
}

__global__ __launch_bounds__(256, 2) void gemm_f16_kernel(float* __restrict__ out) {
    extern __shared__ __align__(1024) char smem[];
    uint32_t sbase = smem_u32(smem);
    uint32_t sdata = sbase + SM_DATA0;
    int tid  = threadIdx.x;
    int wid  = tid >> 5;
    int lane = tid & 31;
    int wm = wid >> 2;        // 0..1  -> M offset wm*64
    int wn = wid & 3;         // 0..3  -> N offset wn*32
    // kk rotation: warps sharing an SMSP (wid, wid+4) get offsets s and s+2
    uint32_t woff = (uint32_t)(((wid & 3) + ((wid >> 2) << 1)) & 3);

    const __half* Ag = g_xh + (size_t)blockIdx.y * BM * K_DIM;
    const __half* Bg = g_wh + (size_t)blockIdx.x * BN * K_DIM;

    if (tid == 0) {
#pragma unroll
        for (int s = 0; s < NSTAGE; s++) {
            MBARRIER_INIT(sbase + s * 16, 256);     // full: .noinc arrive per thread
            MBARRIER_INIT(sbase + s * 16 + 8, 8);   // empty: one arrive per warp
        }
    }
    __syncthreads();

    // ldmatrix address components (verified fragment mapping from R4-R14):
    uint32_t a_row[4], a_xor[4];
#pragma unroll
    for (int mt = 0; mt < 4; mt++) {
        int row = wm * 64 + mt * 16 + (lane & 15);
        a_row[mt] = (uint32_t)row * 128u;
        a_xor[mt] = (uint32_t)(row & 7);
    }
    uint32_t ahi = (uint32_t)(lane >> 4);
    uint32_t b_row[2], b_xor[2];
#pragma unroll
    for (int nt2 = 0; nt2 < 2; nt2++) {
        int row = wn * 32 + nt2 * 16 + (lane & 7) + ((lane >> 4) << 3);
        b_row[nt2] = (uint32_t)row * 128u;
        b_xor[nt2] = (uint32_t)(row & 7);
    }
    uint32_t bhi = (uint32_t)((lane >> 3) & 1);

    float acc[4][4][4];
#pragma unroll
    for (int mt = 0; mt < 4; mt++)
#pragma unroll
        for (int nt = 0; nt < 4; nt++)
#pragma unroll
            for (int r = 0; r < 4; r++) acc[mt][nt][r] = 0.0f;

    // prologue: fill stages 0,1 (first fills: no empty wait needed)
    load_half(tid, sdata + 0 * STAGE_BYTES, Ag, 0);
    load_half(tid, sdata + 0 * STAGE_BYTES + A_BYTES, Bg, 0);
    CP_ASYNC_MBAR_ARRIVE_NOINC(sbase + 0 * 16);
    load_half(tid, sdata + 1 * STAGE_BYTES, Ag, BK);
    load_half(tid, sdata + 1 * STAGE_BYTES + A_BYTES, Bg, BK);
    CP_ASYNC_MBAR_ARRIVE_NOINC(sbase + 1 * 16);

    // pipeline cursors: consumer (chunk i), producer (chunk i+2)
    uint32_t soff_c = 0;                      // stage byte-offset of chunk i
    uint32_t p_full = 0;                      // full parity = (i/3)&1
    uint32_t soff_l = (NSTAGE - 1) * STAGE_BYTES;  // stage of chunk i+2
    uint32_t p_empty = 1;                     // first empty-wait passes
    size_t   lkoff  = (size_t)(NSTAGE - 1) * BK;

#pragma unroll 1
    for (int i = 0; i < NCHUNK; i++) {
        uint32_t mb = sbase + (soff_c >> 15) * 16;
        MBARRIER_WAIT_PARITY(mb, p_full);     // chunk i data visible (acquire)

        uint32_t sa = sdata + soff_c;
        uint32_t sb = sa + A_BYTES;
        bool do_load = i < NCHUNK - (NSTAGE - 1);

#pragma unroll
        for (int kk2 = 0; kk2 < 4; kk2++) {   // 4 x k16, rotated per warp
            uint32_t kk = ((uint32_t)kk2 + woff) & 3u;
            uint32_t af[4][4], bf[2][4];
#pragma unroll
            for (int mt = 0; mt < 4; mt++)
                ldsm4(af[mt], sa + a_row[mt] +
                      (((2u * kk + ahi) ^ a_xor[mt]) << 4));
#pragma unroll
            for (int nt2 = 0; nt2 < 2; nt2++)
                ldsm4(bf[nt2], sb + b_row[nt2] +
                      (((2u * kk + bhi) ^ b_xor[nt2]) << 4));
#pragma unroll
            for (int mt = 0; mt < 4; mt++)
#pragma unroll
                for (int nt = 0; nt < 4; nt++)
                    mma_f16(acc[mt][nt], af[mt],
                            bf[nt >> 1][(nt & 1) ? 2 : 0],
                            bf[nt >> 1][(nt & 1) ? 3 : 1]);

            // producer hoisted to kk-loop midpoint: empty(stage i+2) depends
            // on releases of chunk i-1 (already done in steady state), so the
            // ~140cyc produce segment overlaps the remaining MMA work.
            if (kk2 == 1 && do_load) {
                uint32_t mbl = sbase + (soff_l >> 15) * 16;
                MBARRIER_WAIT_PARITY(mbl + 8, p_empty);   // stage free (acquire)
                uint32_t sl = sdata + soff_l;
                load_half(tid, sl, Ag, lkoff);
                load_half(tid, sl + A_BYTES, Bg, lkoff);
                CP_ASYNC_MBAR_ARRIVE_NOINC(mbl);
            }
        }

        // this warp is done reading stage of chunk i -> release it
        __syncwarp();
        if (lane == 0) MBARRIER_ARRIVE(mb + 8);

        // advance cursors (flip parity on ring wrap)
        soff_c += STAGE_BYTES;
        if (soff_c == NSTAGE * STAGE_BYTES) { soff_c = 0; p_full ^= 1; }
        soff_l += STAGE_BYTES;
        if (soff_l == NSTAGE * STAGE_BYTES) { soff_l = 0; p_empty ^= 1; }
        lkoff += BK;
    }

    // epilogue: direct STG from fragments (c0,c1 contiguous; c2,c3 at row+8)
    int g = lane >> 2, tig = lane & 3;
    size_t orow0 = (size_t)(blockIdx.y * BM + wm * 64 + g) * O_DIM;
    int ocol0 = blockIdx.x * BN + wn * 32 + 2 * tig;
#pragma unroll
    for (int mt = 0; mt < 4; mt++) {
#pragma unroll
        for (int nt = 0; nt < 4; nt++) {
            size_t base = orow0 + (size_t)(mt * 16) * O_DIM + (ocol0 + nt * 8);
            *reinterpret_cast<float2*>(out + base) =
                make_float2(acc[mt][nt][0], acc[mt][nt][1]);
            *reinterpret_cast<float2*>(out + base + (size_t)8 * O_DIM) =
                make_float2(acc[mt][nt][2], acc[mt][nt][3]);
        }
    }
}

// ---------------- launch ----------------
extern "C" void kernel_launch(void* const* d_in, const int* in_sizes, int n_in,
                              void* d_out, int out_size) {
    const float* x = (const float*)d_in[0];   // [4096, 2048]
    const float* w = (const float*)d_in[1];   // [1, 4096, 2048]
    float* out = (float*)d_out;               // [4096, 4096]

    // 1) round both operands to nearest-fp16 (same mantissa as tf32)
    cvt_f16_kernel<<<(B_DIM * K_DIM / 4) / 256, 256>>>(x, w);

    // 2) fp16 mma.sync GEMM, fp32 accumulate, mbarrier pipeline
    cudaFuncSetAttribute(gemm_f16_kernel, cudaFuncAttributeMaxDynamicSharedMemorySize,
                         SMEM_TOTAL);
    dim3 grid(O_DIM / BN, B_DIM / BM);        // (32, 32) = 1024 CTAs
    gemm_f16_kernel<<<grid, 256, SMEM_TOTAL>>>(out);
}

// round 16
// speedup vs baseline: 1.0289x; 1.0289x over previous
#include <cuda_runtime.h>
#include <cuda_fp16.h>
#include <cuda.h>
#include <cstdint>

// ============================================================
// TorchRandomProject: out[4096,4096] = x[4096,2048] @ matrix[0][4096,2048]^T
// fp16 HMMA (same 10-bit mantissa as tf32 => same rel_err), fp32 accum.
// R16: replace per-thread cp.async loads (12 LDGSTS/thread/chunk + address
// ALU) with base-sm_90 TMA: cp.async.bulk.tensor.2d.shared::cta +
// mbarrier complete_tx. CU_TENSOR_MAP_SWIZZLE_128B == the existing
// chunk^(row&7) layout, so ldmatrix addressing is unchanged. Tensormaps
// built per call via cudaGetDriverEntryPoint (no -lcuda link needed),
// passed __grid_constant__. full[s]: count 1 + expect_tx(49152) by tid0;
// empty[s]: count 8 (per-warp release) as in the R14 champion.
// ============================================================

#define B_DIM   4096
#define K_DIM   2048
#define O_DIM   4096

// 32MB device scratch for fp16 operands
__device__ __half g_xh[(size_t)B_DIM * K_DIM];
__device__ __half g_wh[(size_t)O_DIM * K_DIM];

// ---------------- tile config ----------------
#define BM 128
#define BN 128
#define BK 64                       // K halfs per chunk (128B row)
#define NSTAGE 3
#define NCHUNK (K_DIM / BK)         // 32
#define A_BYTES (BM * BK * 2)       // 16384
#define B_BYTES (BN * BK * 2)       // 16384
#define STAGE_BYTES (A_BYTES + B_BYTES)      // 32768 (= 1<<15)
#define SM_DATA0 1024               // stages start here (mbarriers below)
#define SMEM_TOTAL (SM_DATA0 + NSTAGE * STAGE_BYTES)  // 99328 (x2 CTA ok)

// ---------------- PTX helpers ----------------
__device__ __forceinline__ uint32_t smem_u32(const void* p) {
    uint32_t a;
    asm("{ .reg .u64 t; cvta.to.shared.u64 t, %1; cvt.u32.u64 %0, t; }" : "=r"(a) : "l"(p));
    return a;
}

#define MBARRIER_INIT(addr, count) \
    asm volatile("mbarrier.init.shared.b64 [%0], %1;" :: "r"((uint32_t)(addr)), "r"((uint32_t)(count)) : "memory")

#define MBARRIER_ARRIVE(addr) \
    asm volatile("mbarrier.arrive.shared.b64 _, [%0];" :: "r"((uint32_t)(addr)) : "memory")

#define MBARRIER_EXPECT_TX(addr, bytes) \
    asm volatile("mbarrier.arrive.expect_tx.shared.b64 _, [%0], %1;" \
        :: "r"((uint32_t)(addr)), "r"((uint32_t)(bytes)) : "memory")

#define TMA_LOAD_2D(smem_addr, tmap, cx, cy, mbar) \
    asm volatile("cp.async.bulk.tensor.2d.shared::cta.global.tile.mbarrier::complete_tx::bytes " \
        "[%0], [%1, {%2, %3}], [%4];" \
        :: "r"((uint32_t)(smem_addr)), "l"(tmap), "r"((int)(cx)), "r"((int)(cy)), \
           "r"((uint32_t)(mbar)) : "memory")

#define MBARRIER_WAIT_PARITY(addr, parity) do { \
    uint32_t _mbar = (uint32_t)(addr); \
    uint32_t _par = (uint32_t)(parity); \
    uint32_t _done; \
    asm volatile("{\n\t.reg .pred p;\n\t" \
        "mbarrier.try_wait.parity.acquire.cta.shared::cta.b64 p, [%1], %2;\n\t" \
        "selp.b32 %0, 1, 0, p;\n\t}" : "=r"(_done) : "r"(_mbar), "r"(_par) : "memory"); \
    if (!_done) { \
        asm volatile("{\n\t.reg .pred P1;\n\t" \
            "WL_%=:\n\t" \
            "mbarrier.try_wait.parity.acquire.cta.shared::cta.b64 P1, [%0], %1, 0x989680;\n\t" \
            "@P1 bra.uni WD_%=;\n\t" \
            "bra.uni WL_%=;\n\t" \
            "WD_%=:\n\t}" :: "r"(_mbar), "r"(_par) : "memory"); \
    } \
} while (0)

__device__ __forceinline__ void ldsm4(uint32_t r[4], uint32_t addr) {
    asm volatile("ldmatrix.sync.aligned.m8n8.x4.shared.b16 {%0,%1,%2,%3}, [%4];"
                 : "=r"(r[0]), "=r"(r[1]), "=r"(r[2]), "=r"(r[3]) : "r"(addr));
}

__device__ __forceinline__ void mma_f16(float c[4], const uint32_t a[4],
                                        uint32_t b0, uint32_t b1) {
    asm volatile(
        "mma.sync.aligned.m16n8k16.row.col.f32.f16.f16.f32 "
        "{%0,%1,%2,%3}, {%4,%5,%6,%7}, {%8,%9}, {%0,%1,%2,%3};"
        : "+f"(c[0]), "+f"(c[1]), "+f"(c[2]), "+f"(c[3])
        : "r"(a[0]), "r"(a[1]), "r"(a[2]), "r"(a[3]), "r"(b0), "r"(b1));
}

// ---------------- prep: fp32 -> fp16 (rne) ----------------
__global__ void cvt_f16_kernel(const float* __restrict__ x, const float* __restrict__ w) {
    size_t i = (size_t)blockIdx.x * blockDim.x + threadIdx.x;  // over 2M float4
    float4 a = reinterpret_cast<const float4*>(x)[i];
    reinterpret_cast<__half2*>(g_xh)[2 * i + 0] = __floats2half2_rn(a.x, a.y);
    reinterpret_cast<__half2*>(g_xh)[2 * i + 1] = __floats2half2_rn(a.z, a.w);
    float4 b = reinterpret_cast<const float4*>(w)[i];
    reinterpret_cast<__half2*>(g_wh)[2 * i + 0] = __floats2half2_rn(b.x, b.y);
    reinterpret_cast<__half2*>(g_wh)[2 * i + 1] = __floats2half2_rn(b.z, b.w);
}

// ---------------- GEMM ----------------
// mbarriers: full[s] = sbase + s*16 (count 1; tid0 expect_tx + TMA tx),
// empty[s] = +8 (count 8, lane-0 arrive per warp).
// stage data at sbase + SM_DATA0; A then B. TMA SW128 == chunk^(row&7).

__global__ __launch_bounds__(256, 2) void gemm_f16_kernel(
    float* __restrict__ out,
    const __grid_constant__ CUtensorMap tmA,
    const __grid_constant__ CUtensorMap tmB
) {
    extern __shared__ __align__(1024) char smem[];
    uint32_t sbase = smem_u32(smem);
    uint32_t sdata = sbase + SM_DATA0;
    int tid  = threadIdx.x;
    int wid  = tid >> 5;
    int lane = tid & 31;
    int wm = wid >> 2;        // 0..1  -> M offset wm*64
    int wn = wid & 3;         // 0..3  -> N offset wn*32
    // kk rotation: warps sharing an SMSP (wid, wid+4) get offsets s and s+2
    uint32_t woff = (uint32_t)(((wid & 3) + ((wid >> 2) << 1)) & 3);

    int a_cy = blockIdx.y * BM;       // A row-block coordinate
    int b_cy = blockIdx.x * BN;       // B row-block coordinate

    if (tid == 0) {
#pragma unroll
        for (int s = 0; s < NSTAGE; s++) {
            MBARRIER_INIT(sbase + s * 16, 1);       // full: tid0 expect_tx
            MBARRIER_INIT(sbase + s * 16 + 8, 8);   // empty: one arrive per warp
        }
    }
    __syncthreads();

    // prologue: tid0 kicks TMA for stages 0,1 (first fills: no empty wait)
    if (tid == 0) {
        MBARRIER_EXPECT_TX(sbase + 0 * 16, STAGE_BYTES);
        TMA_LOAD_2D(sdata + 0 * STAGE_BYTES,           &tmA, 0,  a_cy, sbase + 0 * 16);
        TMA_LOAD_2D(sdata + 0 * STAGE_BYTES + A_BYTES, &tmB, 0,  b_cy, sbase + 0 * 16);
        MBARRIER_EXPECT_TX(sbase + 1 * 16, STAGE_BYTES);
        TMA_LOAD_2D(sdata + 1 * STAGE_BYTES,           &tmA, BK, a_cy, sbase + 1 * 16);
        TMA_LOAD_2D(sdata + 1 * STAGE_BYTES + A_BYTES, &tmB, BK, b_cy, sbase + 1 * 16);
    }

    // ldmatrix address components (verified fragment mapping from R4-R15):
    uint32_t a_row[4], a_xor[4];
#pragma unroll
    for (int mt = 0; mt < 4; mt++) {
        int row = wm * 64 + mt * 16 + (lane & 15);
        a_row[mt] = (uint32_t)row * 128u;
        a_xor[mt] = (uint32_t)(row & 7);
    }
    uint32_t ahi = (uint32_t)(lane >> 4);
    uint32_t b_row[2], b_xor[2];
#pragma unroll
    for (int nt2 = 0; nt2 < 2; nt2++) {
        int row = wn * 32 + nt2 * 16 + (lane & 7) + ((lane >> 4) << 3);
        b_row[nt2] = (uint32_t)row * 128u;
        b_xor[nt2] = (uint32_t)(row & 7);
    }
    uint32_t bhi = (uint32_t)((lane >> 3) & 1);

    float acc[4][4][4];
#pragma unroll
    for (int mt = 0; mt < 4; mt++)
#pragma unroll
        for (int nt = 0; nt < 4; nt++)
#pragma unroll
            for (int r = 0; r < 4; r++) acc[mt][nt][r] = 0.0f;

    // pipeline cursors: consumer (chunk i), producer (chunk i+2)
    uint32_t soff_c = 0;                      // stage byte-offset of chunk i
    uint32_t p_full = 0;                      // full parity = (i/3)&1
    uint32_t soff_l = (NSTAGE - 1) * STAGE_BYTES;  // stage of chunk i+2
    uint32_t p_empty = 1;                     // first empty-wait passes
    int      lcx    = (NSTAGE - 1) * BK;      // TMA x-coord of produced chunk

#pragma unroll 1
    for (int i = 0; i < NCHUNK; i++) {
        uint32_t mb = sbase + (soff_c >> 15) * 16;
        MBARRIER_WAIT_PARITY(mb, p_full);     // chunk i data visible (acquire)

        uint32_t sa = sdata + soff_c;
        uint32_t sb = sa + A_BYTES;
        bool do_load = i < NCHUNK - (NSTAGE - 1);

#pragma unroll
        for (int kk2 = 0; kk2 < 4; kk2++) {   // 4 x k16, rotated per warp
            uint32_t kk = ((uint32_t)kk2 + woff) & 3u;
            uint32_t af[4][4], bf[2][4];
#pragma unroll
            for (int mt = 0; mt < 4; mt++)
                ldsm4(af[mt], sa + a_row[mt] +
                      (((2u * kk + ahi) ^ a_xor[mt]) << 4));
#pragma unroll
            for (int nt2 = 0; nt2 < 2; nt2++)
                ldsm4(bf[nt2], sb + b_row[nt2] +
                      (((2u * kk + bhi) ^ b_xor[nt2]) << 4));
#pragma unroll
            for (int mt = 0; mt < 4; mt++)
#pragma unroll
                for (int nt = 0; nt < 4; nt++)
                    mma_f16(acc[mt][nt], af[mt],
                            bf[nt >> 1][(nt & 1) ? 2 : 0],
                            bf[nt >> 1][(nt & 1) ? 3 : 1]);

            // producer (tid0 only): empty(stage i+2) depends on releases of
            // chunk i-1, already done in steady state; TMA issue is ~5 instrs.
            if (kk2 == 1 && do_load && tid == 0) {
                uint32_t mbl = sbase + (soff_l >> 15) * 16;
                MBARRIER_WAIT_PARITY(mbl + 8, p_empty);   // stage free (acquire)
                uint32_t sl = sdata + soff_l;
                MBARRIER_EXPECT_TX(mbl, STAGE_BYTES);
                TMA_LOAD_2D(sl,           &tmA, lcx, a_cy, mbl);
                TMA_LOAD_2D(sl + A_BYTES, &tmB, lcx, b_cy, mbl);
            }
        }

        // this warp is done reading stage of chunk i -> release it
        __syncwarp();
        if (lane == 0) MBARRIER_ARRIVE(mb + 8);

        // advance cursors (flip parity on ring wrap)
        soff_c += STAGE_BYTES;
        if (soff_c == NSTAGE * STAGE_BYTES) { soff_c = 0; p_full ^= 1; }
        soff_l += STAGE_BYTES;
        if (soff_l == NSTAGE * STAGE_BYTES) { soff_l = 0; p_empty ^= 1; }
        lcx += BK;
    }

    // epilogue: direct STG from fragments (c0,c1 contiguous; c2,c3 at row+8)
    int g = lane >> 2, tig = lane & 3;
    size_t orow0 = (size_t)(blockIdx.y * BM + wm * 64 + g) * O_DIM;
    int ocol0 = blockIdx.x * BN + wn * 32 + 2 * tig;
#pragma unroll
    for (int mt = 0; mt < 4; mt++) {
#pragma unroll
        for (int nt = 0; nt < 4; nt++) {
            size_t base = orow0 + (size_t)(mt * 16) * O_DIM + (ocol0 + nt * 8);
            *reinterpret_cast<float2*>(out + base) =
                make_float2(acc[mt][nt][0], acc[mt][nt][1]);
            *reinterpret_cast<float2*>(out + base + (size_t)8 * O_DIM) =
                make_float2(acc[mt][nt][2], acc[mt][nt][3]);
        }
    }
}

// ---------------- launch ----------------
typedef CUresult (*PFN_encodeTiled)(
    CUtensorMap*, CUtensorMapDataType, cuuint32_t, void*,
    const cuuint64_t*, const cuuint64_t*, const cuuint32_t*, const cuuint32_t*,
    CUtensorMapInterleave, CUtensorMapSwizzle, CUtensorMapL2promotion,
    CUtensorMapFloatOOBfill);

extern "C" void kernel_launch(void* const* d_in, const int* in_sizes, int n_in,
                              void* d_out, int out_size) {
    const float* x = (const float*)d_in[0];   // [4096, 2048]
    const float* w = (const float*)d_in[1];   // [1, 4096, 2048]
    float* out = (float*)d_out;               // [4096, 4096]

    // 1) round both operands to nearest-fp16 (same mantissa as tf32)
    cvt_f16_kernel<<<(B_DIM * K_DIM / 4) / 256, 256>>>(x, w);

    // 2) build TMA descriptors for the fp16 scratch (deterministic per call)
    void* xh_ptr = nullptr; void* wh_ptr = nullptr;
    cudaGetSymbolAddress(&xh_ptr, g_xh);
    cudaGetSymbolAddress(&wh_ptr, g_wh);

    PFN_encodeTiled encode = nullptr;
    cudaDriverEntryPointQueryResult qr;
    cudaGetDriverEntryPoint("cuTensorMapEncodeTiled", (void**)&encode,
                            cudaEnableDefault, &qr);

    CUtensorMap tmA, tmB;
    cuuint64_t dims[2]    = { (cuuint64_t)K_DIM, (cuuint64_t)B_DIM };
    cuuint64_t strides[1] = { (cuuint64_t)K_DIM * 2 };
    cuuint32_t box[2]     = { (cuuint32_t)BK, (cuuint32_t)BM };   // 128B x 128 rows
    cuuint32_t est[2]     = { 1, 1 };
    encode(&tmA, CU_TENSOR_MAP_DATA_TYPE_FLOAT16, 2, xh_ptr,
           dims, strides, box, est,
           CU_TENSOR_MAP_INTERLEAVE_NONE, CU_TENSOR_MAP_SWIZZLE_128B,
           CU_TENSOR_MAP_L2_PROMOTION_L2_128B, CU_TENSOR_MAP_FLOAT_OOB_FILL_NONE);
    cuuint64_t dimsB[2]   = { (cuuint64_t)K_DIM, (cuuint64_t)O_DIM };
    encode(&tmB, CU_TENSOR_MAP_DATA_TYPE_FLOAT16, 2, wh_ptr,
           dimsB, strides, box, est,
           CU_TENSOR_MAP_INTERLEAVE_NONE, CU_TENSOR_MAP_SWIZZLE_128B,
           CU_TENSOR_MAP_L2_PROMOTION_L2_128B, CU_TENSOR_MAP_FLOAT_OOB_FILL_NONE);

    // 3) fp16 mma.sync GEMM, fp32 accumulate, TMA + mbarrier pipeline
    cudaFuncSetAttribute(gemm_f16_kernel, cudaFuncAttributeMaxDynamicSharedMemorySize,
                         SMEM_TOTAL);
    dim3 grid(O_DIM / BN, B_DIM / BM);        // (32, 32) = 1024 CTAs
    gemm_f16_kernel<<<grid, 256, SMEM_TOTAL>>>(out, tmA, tmB);
}